// round 3
// baseline (speedup 1.0000x reference)
#include <cuda_runtime.h>

// ---------------------------------------------------------------------------
// RelPositionMultiHeadAttention  (B=8, T=1024, H=8, D=64, F=512, L=2047)
// R3 = R2 design with the illegal static guard removed (harness forbids
// static guards; cudaFuncSetAttribute is now called unconditionally, the
// exact pattern that passed in R1).
// rel_shift identity: shifted_bd[a,k] = q_v[a] . P[1023 + k - a]
// ---------------------------------------------------------------------------

#define BB 8
#define TT 1024
#define HH 8
#define DD 64
#define FF 512
#define LL 2047

__device__ float g_Q[BB*HH*TT*DD];
__device__ float g_K[BB*HH*TT*DD];
__device__ float g_V[BB*HH*TT*DD];
__device__ float g_P[HH*LL*DD];
__device__ float g_X[BB*TT*FF];

// ---------------------------------------------------------------------------
// GEMM core: C[m,n] = sum_k A[m,k] * W[n,k] + bias[n],  K = N = 512.
// Tile 128x128, BK=16, 256 threads, 8x8 per thread.
// layout: 0 = row-major MxN, 1 = scatter [B][H][T][D], 2 = [H][L][D]
// ---------------------------------------------------------------------------
__device__ __forceinline__
void gemm_core(const float* __restrict__ A, const float* __restrict__ W,
               const float* __restrict__ bias, float* __restrict__ C,
               int M, int layout, int m0, int n0)
{
    const int K = 512;
    __shared__ float As[16][132];
    __shared__ float Bs[16][132];

    const int tid = threadIdx.x;
    const int tx = tid & 15;
    const int ty = tid >> 4;

    float acc[8][8];
#pragma unroll
    for (int i = 0; i < 8; i++)
#pragma unroll
        for (int j = 0; j < 8; j++) acc[i][j] = 0.0f;

    const int lr = tid >> 1;
    const int lk = (tid & 1) << 3;

    for (int k0 = 0; k0 < K; k0 += 16) {
        float4 a0 = make_float4(0.f,0.f,0.f,0.f), a1 = make_float4(0.f,0.f,0.f,0.f);
        const int gm = m0 + lr;
        if (gm < M) {
            const float4* ap = (const float4*)(A + gm * K + k0 + lk);
            a0 = ap[0]; a1 = ap[1];
        }
        const float4* wp = (const float4*)(W + (n0 + lr) * K + k0 + lk);
        float4 b0 = wp[0], b1 = wp[1];

        __syncthreads();
        As[lk+0][lr] = a0.x; As[lk+1][lr] = a0.y; As[lk+2][lr] = a0.z; As[lk+3][lr] = a0.w;
        As[lk+4][lr] = a1.x; As[lk+5][lr] = a1.y; As[lk+6][lr] = a1.z; As[lk+7][lr] = a1.w;
        Bs[lk+0][lr] = b0.x; Bs[lk+1][lr] = b0.y; Bs[lk+2][lr] = b0.z; Bs[lk+3][lr] = b0.w;
        Bs[lk+4][lr] = b1.x; Bs[lk+5][lr] = b1.y; Bs[lk+6][lr] = b1.z; Bs[lk+7][lr] = b1.w;
        __syncthreads();

#pragma unroll
        for (int kk = 0; kk < 16; kk++) {
            float a[8], b[8];
            *(float4*)(a)     = *(const float4*)&As[kk][ty*8];
            *(float4*)(a + 4) = *(const float4*)&As[kk][ty*8 + 4];
            *(float4*)(b)     = *(const float4*)&Bs[kk][tx*8];
            *(float4*)(b + 4) = *(const float4*)&Bs[kk][tx*8 + 4];
#pragma unroll
            for (int i = 0; i < 8; i++)
#pragma unroll
                for (int j = 0; j < 8; j++)
                    acc[i][j] = fmaf(a[i], b[j], acc[i][j]);
        }
    }

#pragma unroll
    for (int i = 0; i < 8; i++) {
        const int m = m0 + ty*8 + i;
        if (m >= M) continue;
#pragma unroll
        for (int j = 0; j < 8; j++) {
            const int n = n0 + tx*8 + j;
            float v = acc[i][j];
            if (bias) v += bias[n];
            if (layout == 0) {
                C[m * 512 + n] = v;
            } else if (layout == 1) {
                const int b  = m >> 10, t = m & 1023;
                const int hh = n >> 6,  dd = n & 63;
                C[((b * HH + hh) * TT + t) * DD + dd] = v;
            } else {
                const int hh = n >> 6, dd = n & 63;
                C[(hh * LL + m) * DD + dd] = v;
            }
        }
    }
}

// Fused Q/K/V/P projections: z selects the matrix.
__global__ __launch_bounds__(256)
void qkvp_kernel(const float* __restrict__ query, const float* __restrict__ key,
                 const float* __restrict__ value, const float* __restrict__ pos_emb,
                 const float* __restrict__ Wq, const float* __restrict__ bq,
                 const float* __restrict__ Wk, const float* __restrict__ bk,
                 const float* __restrict__ Wv, const float* __restrict__ bv,
                 const float* __restrict__ Wpos)
{
    const int z = blockIdx.z;
    if (z == 3 && blockIdx.y >= 16) return;
    const int m0 = blockIdx.y * 128;
    const int n0 = blockIdx.x * 128;
    if (z == 0)      gemm_core(query,   Wq,   bq,      g_Q, BB*TT, 1, m0, n0);
    else if (z == 1) gemm_core(key,     Wk,   bk,      g_K, BB*TT, 1, m0, n0);
    else if (z == 2) gemm_core(value,   Wv,   bv,      g_V, BB*TT, 1, m0, n0);
    else             gemm_core(pos_emb, Wpos, nullptr, g_P, LL,    2, m0, n0);
}

__global__ __launch_bounds__(256)
void out_gemm_kernel(const float* __restrict__ Wo, const float* __restrict__ bo,
                     float* __restrict__ out)
{
    gemm_core(g_X, Wo, bo, out, BB*TT, 0, blockIdx.y * 128, blockIdx.x * 128);
}

// ---------------------------------------------------------------------------
// Fused attention. Block = (b,h, 128-query tile). 256 threads = 16x16,
// each thread owns 8(q) x 4(k) scores and 8(q) x 4(d) output.
// ---------------------------------------------------------------------------
#define QT_S 132   // Q^T stride
#define KT_S 68    // K^T / V stride
#define PB_S 196   // pos band stride (191 rows used)
#define PR_S 140   // prob matrix stride (128 cols used)

__global__ __launch_bounds__(256, 1)
void attn_kernel(const unsigned char* __restrict__ maskb,
                 const float* __restrict__ Ubias,
                 const float* __restrict__ Vbias)
{
    extern __shared__ float sm[];
    float* Qt  = sm;                    // [64][QT_S]  Q^T  (d-major, 128 q cols)
    float* Kt  = Qt  + DD * QT_S;       // [64][KT_S]  K^T  (d-major, 64 k cols)
    float* Vs  = Kt  + DD * KT_S;       // [64][KT_S]  V    (k-major, 64 d cols)
    float* Pb  = Vs  + DD * KT_S;       // [64][PB_S]  pos band (d-major) / probs [k][PR_S]
    float* uvp = Pb  + DD * PB_S;       // [128]

    const int tid = threadIdx.x;
    const int tx = tid & 15;
    const int ty = tid >> 4;
    const int q0 = blockIdx.x * 128;
    const int bh = blockIdx.y;
    const int b = bh >> 3, h = bh & 7;

    // --- mask dtype sniff (deterministic across all threads) ---
    int mmode;
    {
        bool i32 = true, f32 = true;
#pragma unroll
        for (int i = 0; i < 32; i++) {
            unsigned char c0 = maskb[4*i+0], c1 = maskb[4*i+1];
            unsigned char c2 = maskb[4*i+2], c3 = maskb[4*i+3];
            if (c1 | c2 | c3) i32 = false;
            if (c0 | c1) f32 = false;
            if (!((c2 == 0 && c3 == 0) || (c2 == 0x80 && c3 == 0x3F))) f32 = false;
        }
        mmode = i32 ? 1 : (f32 ? 2 : 0);
    }

    // --- load Q tile transposed + biases ---
    const int qbase = (bh * TT + q0) * DD;
#pragma unroll
    for (int r = 0; r < 8; r++) {
        const int idx = tid + r * 256;
        const int a = idx >> 4, dq = (idx & 15) << 2;
        float4 q4 = *(const float4*)&g_Q[qbase + a * DD + dq];
        Qt[(dq+0)*QT_S + a] = q4.x;
        Qt[(dq+1)*QT_S + a] = q4.y;
        Qt[(dq+2)*QT_S + a] = q4.z;
        Qt[(dq+3)*QT_S + a] = q4.w;
    }
    if (tid < 64)        uvp[tid] = Ubias[h * DD + tid];
    else if (tid < 128)  uvp[tid] = Vbias[h * DD + tid - 64];

    float mi[8], li[8], O[8][4];
#pragma unroll
    for (int i = 0; i < 8; i++) {
        mi[i] = -1e30f; li[i] = 0.0f;
#pragma unroll
        for (int j = 0; j < 4; j++) O[i][j] = 0.0f;
    }

    const int pbase = 120 + tx * 4 - ty * 8;   // band offset, 16B-aligned, >= 0

    for (int kt = 0; kt < 16; kt++) {
        __syncthreads();   // prior iteration done with Kt/Vs/Pb; Qt/uv visible

        // --- load K^T, V ---
        const int kvbase = (bh * TT + kt * 64) * DD;
#pragma unroll
        for (int r = 0; r < 4; r++) {
            const int idx = tid + r * 256;
            const int k = idx >> 4, dq = (idx & 15) << 2;
            float4 k4 = *(const float4*)&g_K[kvbase + k * DD + dq];
            Kt[(dq+0)*KT_S + k] = k4.x;
            Kt[(dq+1)*KT_S + k] = k4.y;
            Kt[(dq+2)*KT_S + k] = k4.z;
            Kt[(dq+3)*KT_S + k] = k4.w;
            float4 v4 = *(const float4*)&g_V[kvbase + k * DD + dq];
            *(float4*)&Vs[k * KT_S + dq] = v4;
        }
        // --- load pos band: rows l in [896 + k0 - q0, +191), transposed ---
        const int lmin = 896 + kt * 64 - q0;
        const int pgbase = (h * LL + lmin) * DD;
#pragma unroll
        for (int r = 0; r < 12; r++) {
            const int idx = tid + r * 256;
            const int ll = idx >> 4, dq = (idx & 15) << 2;
            if (ll < 191) {
                float4 p4 = *(const float4*)&g_P[pgbase + ll * DD + dq];
                Pb[(dq+0)*PB_S + ll] = p4.x;
                Pb[(dq+1)*PB_S + ll] = p4.y;
                Pb[(dq+2)*PB_S + ll] = p4.z;
                Pb[(dq+3)*PB_S + ll] = p4.w;
            }
        }
        __syncthreads();

        // --- scores: AC + BD ---
        float s[8][4];
#pragma unroll
        for (int i = 0; i < 8; i++)
#pragma unroll
            for (int j = 0; j < 4; j++) s[i][j] = 0.0f;

#pragma unroll 2
        for (int d = 0; d < DD; d++) {
            float qa[8], kk[4], pv[12];
            *(float4*)(qa)     = *(const float4*)&Qt[d * QT_S + ty * 8];
            *(float4*)(qa + 4) = *(const float4*)&Qt[d * QT_S + ty * 8 + 4];
            *(float4*)(kk)     = *(const float4*)&Kt[d * KT_S + tx * 4];
            *(float4*)(pv)     = *(const float4*)&Pb[d * PB_S + pbase];
            *(float4*)(pv + 4) = *(const float4*)&Pb[d * PB_S + pbase + 4];
            *(float4*)(pv + 8) = *(const float4*)&Pb[d * PB_S + pbase + 8];
            const float u = uvp[d], vv = uvp[64 + d];
#pragma unroll
            for (int i = 0; i < 8; i++) {
                const float qu = qa[i] + u;
                const float qv = qa[i] + vv;
#pragma unroll
                for (int j = 0; j < 4; j++) {
                    s[i][j] = fmaf(qu, kk[j], s[i][j]);
                    s[i][j] = fmaf(qv, pv[7 + j - i], s[i][j]);
                }
            }
        }
        __syncthreads();   // done reading band (Pb) and Kt

        // --- scale + mask ---
        const int kg0 = kt * 64 + tx * 4;
#pragma unroll
        for (int i = 0; i < 8; i++) {
            const int ridx = (b * TT + q0 + ty * 8 + i) * TT + kg0;
            int mk[4];
            if (mmode == 1) {
                int4 m4 = *(const int4*)((const int*)maskb + ridx);
                mk[0] = m4.x != 0; mk[1] = m4.y != 0; mk[2] = m4.z != 0; mk[3] = m4.w != 0;
            } else if (mmode == 2) {
                float4 m4 = *(const float4*)((const float*)maskb + ridx);
                mk[0] = m4.x != 0.f; mk[1] = m4.y != 0.f; mk[2] = m4.z != 0.f; mk[3] = m4.w != 0.f;
            } else {
                unsigned int w = *(const unsigned int*)(maskb + ridx);
                mk[0] = (w & 0xFFu) != 0; mk[1] = (w & 0xFF00u) != 0;
                mk[2] = (w & 0xFF0000u) != 0; mk[3] = (w & 0xFF000000u) != 0;
            }
#pragma unroll
            for (int j = 0; j < 4; j++)
                s[i][j] = mk[j] ? -10000.0f : s[i][j] * 0.125f;
        }

        // --- online softmax ---
#pragma unroll
        for (int i = 0; i < 8; i++) {
            float rm = fmaxf(fmaxf(s[i][0], s[i][1]), fmaxf(s[i][2], s[i][3]));
#pragma unroll
            for (int o = 8; o >= 1; o >>= 1)
                rm = fmaxf(rm, __shfl_xor_sync(0xffffffffu, rm, o));
            const float mnew  = fmaxf(mi[i], rm);
            const float alpha = __expf(mi[i] - mnew);
            float rsum = 0.0f;
#pragma unroll
            for (int j = 0; j < 4; j++) {
                float p = (s[i][j] == -10000.0f) ? 0.0f : __expf(s[i][j] - mnew);
                s[i][j] = p;
                rsum += p;
            }
#pragma unroll
            for (int o = 8; o >= 1; o >>= 1)
                rsum += __shfl_xor_sync(0xffffffffu, rsum, o);
            li[i] = li[i] * alpha + rsum;
            mi[i] = mnew;
            O[i][0] *= alpha; O[i][1] *= alpha; O[i][2] *= alpha; O[i][3] *= alpha;
        }

        // --- store probs transposed [k][a] into Pb ---
#pragma unroll
        for (int j = 0; j < 4; j++)
#pragma unroll
            for (int i = 0; i < 8; i++)
                Pb[(tx*4 + j) * PR_S + ty*8 + i] = s[i][j];
        __syncthreads();

        // --- O += P @ V ---
#pragma unroll 2
        for (int k = 0; k < 64; k++) {
            float pa[8], va[4];
            *(float4*)(pa)     = *(const float4*)&Pb[k * PR_S + ty * 8];
            *(float4*)(pa + 4) = *(const float4*)&Pb[k * PR_S + ty * 8 + 4];
            *(float4*)(va)     = *(const float4*)&Vs[k * KT_S + tx * 4];
#pragma unroll
            for (int i = 0; i < 8; i++)
#pragma unroll
                for (int j = 0; j < 4; j++)
                    O[i][j] = fmaf(pa[i], va[j], O[i][j]);
        }
    }

    // --- epilogue ---
#pragma unroll
    for (int i = 0; i < 8; i++) {
        const float invl = (li[i] > 0.0f) ? (1.0f / li[i]) : 0.0f;
        float4 o4 = make_float4(O[i][0]*invl, O[i][1]*invl, O[i][2]*invl, O[i][3]*invl);
        *(float4*)&g_X[(b * TT + q0 + ty*8 + i) * FF + h * DD + tx * 4] = o4;
    }
}

// ---------------------------------------------------------------------------
extern "C" void kernel_launch(void* const* d_in, const int* in_sizes, int n_in,
                              void* d_out, int out_size)
{
    const float* query   = (const float*)d_in[0];
    const float* key     = (const float*)d_in[1];
    const float* value   = (const float*)d_in[2];
    const unsigned char* mask = (const unsigned char*)d_in[3];
    const float* pos_emb = (const float*)d_in[4];
    const float* Wq  = (const float*)d_in[5];
    const float* bq  = (const float*)d_in[6];
    const float* Wk  = (const float*)d_in[7];
    const float* bk  = (const float*)d_in[8];
    const float* Wv  = (const float*)d_in[9];
    const float* bv  = (const float*)d_in[10];
    const float* Wpos= (const float*)d_in[11];
    const float* Wo  = (const float*)d_in[12];
    const float* bo  = (const float*)d_in[13];
    const float* pbu = (const float*)d_in[14];
    const float* pbv = (const float*)d_in[15];
    float* out = (float*)d_out;

    qkvp_kernel<<<dim3(4, 64, 4), 256>>>(query, key, value, pos_emb,
                                         Wq, bq, Wk, bk, Wv, bv, Wpos);

    const size_t smem = (size_t)(DD*QT_S + DD*KT_S*2 + DD*PB_S + 128) * sizeof(float);
    cudaFuncSetAttribute((const void*)attn_kernel,
                         cudaFuncAttributeMaxDynamicSharedMemorySize, (int)smem);
    attn_kernel<<<dim3(8, 64), 256, smem>>>(mask, pbu, pbv);

    out_gemm_kernel<<<dim3(4, 64), 256>>>(Wo, bo, out);
}

// round 6
// speedup vs baseline: 1.4412x; 1.4412x over previous
#include <cuda_runtime.h>
#include <cuda_bf16.h>
#include <cstdint>

// ---------------------------------------------------------------------------
// RelPositionMultiHeadAttention  (B=8, T=1024, H=8, D=64, F=512, L=2047)
// R6: harness target is sm_100 (NOT sm_100a) -> tcgen05 unavailable.
//     Projections use portable warp-level mma.sync bf16x3 (HMMA) instead.
//     Attention = R1 proven SIMT kernel.
// rel_shift identity: shifted_bd[a,k] = q_v[a] . P[1023 + k - a]
// ---------------------------------------------------------------------------

#define BB 8
#define TT 1024
#define HH 8
#define DD 64
#define FF 512
#define LL 2047

__device__ float g_Q[BB*HH*TT*DD];
__device__ float g_K[BB*HH*TT*DD];
__device__ float g_V[BB*HH*TT*DD];
__device__ float g_P[HH*LL*DD];
__device__ float g_X[BB*TT*FF];

// ========================= helpers =========================================
__device__ __forceinline__ uint32_t smem_u32(const void* p) {
    uint32_t a;
    asm("{ .reg .u64 t; cvta.to.shared.u64 t, %1; cvt.u32.u64 %0, t; }" : "=r"(a) : "l"(p));
    return a;
}
__device__ __forceinline__ void ldm4(uint32_t* r, uint32_t addr) {
    asm volatile("ldmatrix.sync.aligned.m8n8.x4.shared.b16 {%0,%1,%2,%3}, [%4];"
                 : "=r"(r[0]), "=r"(r[1]), "=r"(r[2]), "=r"(r[3]) : "r"(addr));
}
__device__ __forceinline__ void mma16816(float* d, const uint32_t* a, const uint32_t* b) {
    asm volatile("mma.sync.aligned.m16n8k16.row.col.f32.bf16.bf16.f32 "
                 "{%0,%1,%2,%3}, {%4,%5,%6,%7}, {%8,%9}, {%0,%1,%2,%3};"
                 : "+f"(d[0]), "+f"(d[1]), "+f"(d[2]), "+f"(d[3])
                 : "r"(a[0]), "r"(a[1]), "r"(a[2]), "r"(a[3]), "r"(b[0]), "r"(b[1]));
}
__device__ __forceinline__ uint32_t bf16pack(float x, float y) {
    __nv_bfloat162 t = __floats2bfloat162_rn(x, y);
    return *reinterpret_cast<uint32_t*>(&t);
}

// ========================= mma.sync GEMM ===================================
// C[m,n] = sum_k A[m,k]*W[n,k] + bias[n], K=N=512.
// Tile 128x128, BK=32, 8 warps (2m x 4n), warp tile 64x32.
// bf16x3 split: D = Ah.Bh + Ah.Bl + Al.Bh (fp32 accumulate).
// smem rows padded to 80B -> ldmatrix phases conflict-free.
#define RS 80   // bytes per 32-elem bf16 row

__device__ __forceinline__
void store_c(float* __restrict__ C, int layout, int m, int n, float2 v)
{
    if (layout == 0) {
        *(float2*)&C[m * 512 + n] = v;
    } else if (layout == 1) {
        const int b = m >> 10, t = m & 1023;
        const int h = n >> 6,  d = n & 63;
        *(float2*)&C[((b * HH + h) * TT + t) * DD + d] = v;
    } else {
        const int h = n >> 6, d = n & 63;
        *(float2*)&C[(h * LL + m) * DD + d] = v;
    }
}

__device__ __forceinline__
void gemm_mma_core(const float* __restrict__ A, const float* __restrict__ W,
                   const float* __restrict__ bias, float* __restrict__ C,
                   int M, int layout, int m0, int n0)
{
    __shared__ __align__(16) unsigned char smbuf[4 * 128 * RS];
    const uint32_t sb = smem_u32(smbuf);
    const uint32_t oAh = 0, oAl = 128*RS, oWh = 2*128*RS, oWl = 3*128*RS;

    const int tid  = threadIdx.x;
    const int lane = tid & 31;
    const int wid  = tid >> 5;
    const int wm0  = (wid & 1) * 64;    // warp m offset in tile
    const int wn0  = (wid >> 1) * 32;   // warp n offset in tile

    float acc[4][4][4];
#pragma unroll
    for (int i = 0; i < 4; i++)
#pragma unroll
        for (int j = 0; j < 4; j++)
#pragma unroll
            for (int t = 0; t < 4; t++) acc[i][j][t] = 0.0f;

    const int lrow = tid >> 3;          // 0..31
    const int lc   = (tid & 7) * 4;     // 0..28

    for (int k0 = 0; k0 < 512; k0 += 32) {
        __syncthreads();   // previous iteration's ldmatrix reads done
#pragma unroll
        for (int p = 0; p < 4; p++) {
            const int row = p * 32 + lrow;
            const uint32_t so = (uint32_t)(row * RS + lc * 2);

            float4 a = make_float4(0.f, 0.f, 0.f, 0.f);
            const int gm = m0 + row;
            if (gm < M) a = *(const float4*)&A[gm * 512 + k0 + lc];
            float h0 = __bfloat162float(__float2bfloat16(a.x));
            float h1 = __bfloat162float(__float2bfloat16(a.y));
            float h2 = __bfloat162float(__float2bfloat16(a.z));
            float h3 = __bfloat162float(__float2bfloat16(a.w));
            *(uint2*)(smbuf + oAh + so) = make_uint2(bf16pack(h0, h1), bf16pack(h2, h3));
            *(uint2*)(smbuf + oAl + so) = make_uint2(bf16pack(a.x - h0, a.y - h1),
                                                     bf16pack(a.z - h2, a.w - h3));

            float4 w = *(const float4*)&W[(n0 + row) * 512 + k0 + lc];
            h0 = __bfloat162float(__float2bfloat16(w.x));
            h1 = __bfloat162float(__float2bfloat16(w.y));
            h2 = __bfloat162float(__float2bfloat16(w.z));
            h3 = __bfloat162float(__float2bfloat16(w.w));
            *(uint2*)(smbuf + oWh + so) = make_uint2(bf16pack(h0, h1), bf16pack(h2, h3));
            *(uint2*)(smbuf + oWl + so) = make_uint2(bf16pack(w.x - h0, w.y - h1),
                                                     bf16pack(w.z - h2, w.w - h3));
        }
        __syncthreads();

#pragma unroll
        for (int ks = 0; ks < 2; ks++) {
            // A fragments: rows wm0 + i*16 + (lane&7) + (lane&8); k-chunk by lane>>4
            uint32_t ah[4][4], al[4][4];
            const uint32_t kbA = (uint32_t)(ks * 32 + ((lane >> 4) & 1) * 16);
#pragma unroll
            for (int i = 0; i < 4; i++) {
                const uint32_t r = (uint32_t)(wm0 + i * 16 + (lane & 7) + (lane & 8));
                ldm4(ah[i], sb + oAh + r * RS + kbA);
                ldm4(al[i], sb + oAl + r * RS + kbA);
            }
            const uint32_t kbB = (uint32_t)(ks * 32 + ((lane >> 3) & 1) * 16);
#pragma unroll
            for (int j2 = 0; j2 < 2; j2++) {
                // B fragments: two n8 tiles per ldmatrix.x4
                uint32_t wh[4], wl[4];
                const uint32_t r = (uint32_t)(wn0 + j2 * 16 + (lane & 7) + ((lane >> 4) << 3));
                ldm4(wh, sb + oWh + r * RS + kbB);
                ldm4(wl, sb + oWl + r * RS + kbB);
#pragma unroll
                for (int i = 0; i < 4; i++) {
                    mma16816(acc[i][j2*2+0], ah[i], wh + 0);
                    mma16816(acc[i][j2*2+0], ah[i], wl + 0);
                    mma16816(acc[i][j2*2+0], al[i], wh + 0);
                    mma16816(acc[i][j2*2+1], ah[i], wh + 2);
                    mma16816(acc[i][j2*2+1], ah[i], wl + 2);
                    mma16816(acc[i][j2*2+1], al[i], wh + 2);
                }
            }
        }
    }

    // ---- epilogue ----
#pragma unroll
    for (int i = 0; i < 4; i++) {
        const int row = m0 + wm0 + i * 16 + (lane >> 2);
#pragma unroll
        for (int j = 0; j < 4; j++) {
            const int col = n0 + wn0 + j * 8 + (lane & 3) * 2;
            float b0 = 0.f, b1 = 0.f;
            if (bias) { b0 = bias[col]; b1 = bias[col + 1]; }
            if (row < M)
                store_c(C, layout, row, col,
                        make_float2(acc[i][j][0] + b0, acc[i][j][1] + b1));
            if (row + 8 < M)
                store_c(C, layout, row + 8, col,
                        make_float2(acc[i][j][2] + b0, acc[i][j][3] + b1));
        }
    }
}

__global__ __launch_bounds__(256)
void mm_qkvp_kernel(const float* __restrict__ query, const float* __restrict__ key,
                    const float* __restrict__ value, const float* __restrict__ pos_emb,
                    const float* __restrict__ Wq, const float* __restrict__ bq,
                    const float* __restrict__ Wk, const float* __restrict__ bk,
                    const float* __restrict__ Wv, const float* __restrict__ bv,
                    const float* __restrict__ Wpos)
{
    const int z = blockIdx.z;
    if (z == 3 && blockIdx.y >= 16) return;
    const int m0 = blockIdx.y * 128;
    const int n0 = blockIdx.x * 128;
    if (z == 0)      gemm_mma_core(query,   Wq,   bq,      g_Q, BB*TT, 1, m0, n0);
    else if (z == 1) gemm_mma_core(key,     Wk,   bk,      g_K, BB*TT, 1, m0, n0);
    else if (z == 2) gemm_mma_core(value,   Wv,   bv,      g_V, BB*TT, 1, m0, n0);
    else             gemm_mma_core(pos_emb, Wpos, nullptr, g_P, LL,    2, m0, n0);
}

__global__ __launch_bounds__(256)
void mm_out_kernel(const float* __restrict__ Wo, const float* __restrict__ bo,
                   float* __restrict__ out)
{
    gemm_mma_core(g_X, Wo, bo, out, BB*TT, 0, blockIdx.y * 128, blockIdx.x * 128);
}

// ========================= attention (R1, proven) ==========================
#define SQ 68
#define SPB 132

__device__ __forceinline__ int mask_get(const unsigned char* mb, int mode, int idx)
{
    if (mode == 1) return ((const int*)mb)[idx] != 0;
    if (mode == 2) return ((const float*)mb)[idx] != 0.0f;
    return mb[idx] != 0;
}

__global__ __launch_bounds__(256, 2)
void attn_kernel(const unsigned char* __restrict__ maskb,
                 const float* __restrict__ Ubias,
                 const float* __restrict__ Vbias)
{
    extern __shared__ float sm[];
    float* Qt  = sm;                 // [D][SQ]   Q tile, d-major
    float* KPt = Qt  + DD * SQ;      // [D][SQ]   K tile (d-major) / probs [k][a]
    float* Vs  = KPt + DD * SQ;      // [k][SQ]   V tile, k-major
    float* Pb  = Vs  + DD * SQ;      // [D][SPB]  P band, d-major, 127 cols
    float* uv  = Pb  + DD * SPB;     // [128]

    const int tid = threadIdx.x;
    const int tx = tid & 15;
    const int ty = tid >> 4;
    const int q0 = blockIdx.x * 64;
    const int bh = blockIdx.y;
    const int b = bh >> 3, h = bh & 7;

    int mmode;
    {
        bool i32 = true, f32 = true;
#pragma unroll
        for (int i = 0; i < 32; i++) {
            unsigned char c0 = maskb[4*i+0], c1 = maskb[4*i+1];
            unsigned char c2 = maskb[4*i+2], c3 = maskb[4*i+3];
            if (c1 | c2 | c3) i32 = false;
            if (c0 | c1) f32 = false;
            if (!((c2 == 0 && c3 == 0) || (c2 == 0x80 && c3 == 0x3F))) f32 = false;
        }
        mmode = i32 ? 1 : (f32 ? 2 : 0);
    }

    const int qbase = (bh * TT + q0) * DD;
#pragma unroll
    for (int r = 0; r < 4; r++) {
        const int idx = tid + r * 256;
        const int a = idx >> 4, dq = (idx & 15) << 2;
        float4 q4 = *(const float4*)&g_Q[qbase + a * DD + dq];
        Qt[(dq+0)*SQ + a] = q4.x;
        Qt[(dq+1)*SQ + a] = q4.y;
        Qt[(dq+2)*SQ + a] = q4.z;
        Qt[(dq+3)*SQ + a] = q4.w;
    }
    if (tid < 64)        uv[tid] = Ubias[h * DD + tid];
    else if (tid < 128)  uv[tid] = Vbias[h * DD + tid - 64];

    float mi[4], li[4], O[4][4];
#pragma unroll
    for (int i = 0; i < 4; i++) {
        mi[i] = -1e30f; li[i] = 0.0f;
#pragma unroll
        for (int j = 0; j < 4; j++) O[i][j] = 0.0f;
    }

    for (int kt = 0; kt < 16; kt++) {
        __syncthreads();

        const int kvbase = (bh * TT + kt * 64) * DD;
#pragma unroll
        for (int r = 0; r < 4; r++) {
            const int idx = tid + r * 256;
            const int k = idx >> 4, dq = (idx & 15) << 2;
            float4 k4 = *(const float4*)&g_K[kvbase + k * DD + dq];
            KPt[(dq+0)*SQ + k] = k4.x;
            KPt[(dq+1)*SQ + k] = k4.y;
            KPt[(dq+2)*SQ + k] = k4.z;
            KPt[(dq+3)*SQ + k] = k4.w;
            float4 v4 = *(const float4*)&g_V[kvbase + k * DD + dq];
            *(float4*)&Vs[k * SQ + dq] = v4;
        }
        const int lbase = 1023 + kt * 64 - q0;
        const int pbase = (h * LL + (lbase - 63)) * DD;
#pragma unroll
        for (int r = 0; r < 8; r++) {
            const int idx = tid + r * 256;
            const int ll = idx >> 4, dq = (idx & 15) << 2;
            if (ll < 127) {
                float4 p4 = *(const float4*)&g_P[pbase + ll * DD + dq];
                Pb[(dq+0)*SPB + ll] = p4.x;
                Pb[(dq+1)*SPB + ll] = p4.y;
                Pb[(dq+2)*SPB + ll] = p4.z;
                Pb[(dq+3)*SPB + ll] = p4.w;
            }
        }
        __syncthreads();

        float s[4][4];
#pragma unroll
        for (int i = 0; i < 4; i++)
#pragma unroll
            for (int j = 0; j < 4; j++) s[i][j] = 0.0f;

#pragma unroll 4
        for (int d = 0; d < DD; d++) {
            float4 q4 = *(const float4*)&Qt[d * SQ + ty * 4];
            float4 k4 = *(const float4*)&KPt[d * SQ + tx * 4];
            const float u = uv[d], v = uv[64 + d];
            const float* pbp = &Pb[d * SPB + 60 + (tx - ty) * 4];
            float pv[7];
#pragma unroll
            for (int t = 0; t < 7; t++) pv[t] = pbp[t];
            float qa[4] = {q4.x, q4.y, q4.z, q4.w};
            float kk[4] = {k4.x, k4.y, k4.z, k4.w};
#pragma unroll
            for (int i = 0; i < 4; i++) {
                const float qu = qa[i] + u;
                const float qv = qa[i] + v;
#pragma unroll
                for (int j = 0; j < 4; j++) {
                    s[i][j] = fmaf(qu, kk[j], s[i][j]);
                    s[i][j] = fmaf(qv, pv[3 + j - i], s[i][j]);
                }
            }
        }
        __syncthreads();

        const int kg0 = kt * 64 + tx * 4;
#pragma unroll
        for (int i = 0; i < 4; i++) {
            const int ridx = (b * TT + q0 + ty * 4 + i) * TT + kg0;
#pragma unroll
            for (int j = 0; j < 4; j++) {
                const int mk = mask_get(maskb, mmode, ridx + j);
                s[i][j] = mk ? -10000.0f : s[i][j] * 0.125f;
            }
        }

#pragma unroll
        for (int i = 0; i < 4; i++) {
            float rm = fmaxf(fmaxf(s[i][0], s[i][1]), fmaxf(s[i][2], s[i][3]));
#pragma unroll
            for (int o = 8; o >= 1; o >>= 1)
                rm = fmaxf(rm, __shfl_xor_sync(0xffffffffu, rm, o));
            const float mnew  = fmaxf(mi[i], rm);
            const float alpha = __expf(mi[i] - mnew);
            float rsum = 0.0f;
#pragma unroll
            for (int j = 0; j < 4; j++) {
                float p = (s[i][j] == -10000.0f) ? 0.0f : __expf(s[i][j] - mnew);
                s[i][j] = p;
                rsum += p;
            }
#pragma unroll
            for (int o = 8; o >= 1; o >>= 1)
                rsum += __shfl_xor_sync(0xffffffffu, rsum, o);
            li[i] = li[i] * alpha + rsum;
            mi[i] = mnew;
            O[i][0] *= alpha; O[i][1] *= alpha; O[i][2] *= alpha; O[i][3] *= alpha;
        }

#pragma unroll
        for (int i = 0; i < 4; i++)
#pragma unroll
            for (int j = 0; j < 4; j++)
                KPt[(tx*4 + j) * SQ + ty*4 + i] = s[i][j];
        __syncthreads();

#pragma unroll 8
        for (int k = 0; k < 64; k++) {
            float4 p4 = *(const float4*)&KPt[k * SQ + ty * 4];
            float4 v4 = *(const float4*)&Vs[k * SQ + tx * 4];
            float pa[4] = {p4.x, p4.y, p4.z, p4.w};
            float va[4] = {v4.x, v4.y, v4.z, v4.w};
#pragma unroll
            for (int i = 0; i < 4; i++)
#pragma unroll
                for (int j = 0; j < 4; j++)
                    O[i][j] = fmaf(pa[i], va[j], O[i][j]);
        }
    }

#pragma unroll
    for (int i = 0; i < 4; i++) {
        const float invl = (li[i] > 0.0f) ? (1.0f / li[i]) : 0.0f;
        float4 o4 = make_float4(O[i][0]*invl, O[i][1]*invl, O[i][2]*invl, O[i][3]*invl);
        *(float4*)&g_X[(b * TT + q0 + ty*4 + i) * FF + h * DD + tx * 4] = o4;
    }
}

// ========================= launcher ========================================
extern "C" void kernel_launch(void* const* d_in, const int* in_sizes, int n_in,
                              void* d_out, int out_size)
{
    const float* query   = (const float*)d_in[0];
    const float* key     = (const float*)d_in[1];
    const float* value   = (const float*)d_in[2];
    const unsigned char* mask = (const unsigned char*)d_in[3];
    const float* pos_emb = (const float*)d_in[4];
    const float* Wq  = (const float*)d_in[5];
    const float* bq  = (const float*)d_in[6];
    const float* Wk  = (const float*)d_in[7];
    const float* bk  = (const float*)d_in[8];
    const float* Wv  = (const float*)d_in[9];
    const float* bv  = (const float*)d_in[10];
    const float* Wpos= (const float*)d_in[11];
    const float* Wo  = (const float*)d_in[12];
    const float* bo  = (const float*)d_in[13];
    const float* pbu = (const float*)d_in[14];
    const float* pbv = (const float*)d_in[15];
    float* out = (float*)d_out;

    mm_qkvp_kernel<<<dim3(4, 64, 4), 256>>>(query, key, value, pos_emb,
                                            Wq, bq, Wk, bk, Wv, bv, Wpos);

    const size_t smem = (size_t)(DD*SQ*3 + DD*SPB + 128) * sizeof(float);
    cudaFuncSetAttribute((const void*)attn_kernel,
                         cudaFuncAttributeMaxDynamicSharedMemorySize, (int)smem);
    attn_kernel<<<dim3(16, 64), 256, smem>>>(mask, pbu, pbv);

    mm_out_kernel<<<dim3(4, 64), 256>>>(Wo, bo, out);
}